// round 4
// baseline (speedup 1.0000x reference)
#include <cuda_runtime.h>
#include <cuda_bf16.h>
#include <cstdint>

// ---------------------------------------------------------------------------
// W8A8 dynamic-quant linear:  y = (q8(x) @ W^T) * act_scale * w_scale + bias
// TOK=4096, K=4096, OUT(N)=12288
//
// Round 4: rel_err was bit-identical across two different MMA paths ->
// shared-data-path bug. Prime suspect: harness transports int8 weight as a
// wider dtype (its documented dtypes are f32/i32/bf16 only). Add device-side
// weight format autodetect (int32/f32/bf16/raw-int8) + repack to int8
// scratch; GEMM (round-3 IMMA m16n8k16, verified fragment model) unchanged.
// ---------------------------------------------------------------------------

#define TOK   4096
#define KDIM  4096
#define NDIM  12288

#define TILE_M 128
#define TILE_N 256
#define KCH    128
#define NCHUNK (KDIM / KCH)      // 32
#define NSTAGE 3

#define ROWB   144               // 128 B K-chunk + 16 B pad (conflict-free LDS)
#define A_BYTES (TILE_M * ROWB)  // 18432
#define B_BYTES (TILE_N * ROWB)  // 36864
#define STAGE_BYTES (A_BYTES + B_BYTES)   // 55296

// SMEM layout (bytes)
#define SM_WS 0                  // 256 floats
#define SM_BS 1024               // 256 floats
#define SM_AB 2048               // NSTAGE stages
#define SMEM_TOTAL (SM_AB + NSTAGE * STAGE_BYTES)   // 167936

#define W_ELEMS ((size_t)NDIM * KDIM)    // 50331648

// Scratch (module globals -- allocation-free per harness rules)
__device__ int8_t g_xq[(size_t)TOK * KDIM];
__device__ int8_t g_w8[W_ELEMS];
__device__ float  g_ascale[TOK];
__device__ int    g_wmode;       // 0=int8 raw, 1=int32, 2=bf16, 3=f32

// ---------------------------------------------------------------------------
__device__ __forceinline__ uint32_t smem_u32(const void* p) {
    uint32_t a;
    asm("{ .reg .u64 t; cvta.to.shared.u64 t, %1; cvt.u32.u64 %0, t; }" : "=r"(a) : "l"(p));
    return a;
}

__device__ __forceinline__ void cp16(uint32_t dst, const void* src) {
    asm volatile("cp.async.cg.shared.global [%0], [%1], 16;" :: "r"(dst), "l"(src));
}

__device__ __forceinline__ uint32_t lds32(uint32_t addr) {
    uint32_t v;
    asm volatile("ld.shared.b32 %0, [%1];" : "=r"(v) : "r"(addr));
    return v;
}

__device__ __forceinline__ void mma_s8_k16(int* c, uint32_t a0, uint32_t a1, uint32_t b0) {
    asm volatile(
        "mma.sync.aligned.m16n8k16.row.col.s32.s8.s8.s32 "
        "{%0,%1,%2,%3}, {%4,%5}, {%6}, {%0,%1,%2,%3};"
        : "+r"(c[0]), "+r"(c[1]), "+r"(c[2]), "+r"(c[3])
        : "r"(a0), "r"(a1), "r"(b0));
}

// ---------------------------------------------------------------------------
// Weight format autodetect: 1024 samples, modes are bit-pattern disjoint for
// random weights in [-128,127].
// ---------------------------------------------------------------------------
__global__ void detect_kernel(const void* w) {
    __shared__ int ok32, okf32, okbf;
    int tid = threadIdx.x;
    if (tid == 0) { ok32 = 1; okf32 = 1; okbf = 1; }
    __syncthreads();
    const int*            wi = (const int*)w;
    const float*          wf = (const float*)w;
    const __nv_bfloat16*  wb = (const __nv_bfloat16*)w;
#pragma unroll
    for (int i = 0; i < 4; i++) {
        int idx = tid * 4 + i;               // 0..1023
        int v = wi[idx];
        if (v < -128 || v > 127) ok32 = 0;   // racy benign write
        float f = wf[idx];
        if (!(f == rintf(f)) || f < -128.0f || f > 127.0f) okf32 = 0;
        float b = __bfloat162float(wb[idx]);
        if (!(b == rintf(b)) || b < -128.0f || b > 127.0f) okbf = 0;
    }
    __syncthreads();
    if (tid == 0)
        g_wmode = ok32 ? 1 : (okf32 ? 3 : (okbf ? 2 : 0));
}

// Repack weight to canonical int8 in g_w8. Each thread emits 16 bytes.
__global__ void __launch_bounds__(256) pack_kernel(const void* w) {
    size_t g = (size_t)blockIdx.x * blockDim.x + threadIdx.x;   // group of 16 elems
    if (g * 16 >= W_ELEMS) return;
    int mode = g_wmode;
    int8_t o[16];
    if (mode == 0) {
        *(int4*)o = ((const int4*)w)[g];
    } else if (mode == 1) {
        const int4* wi = (const int4*)w + g * 4;
#pragma unroll
        for (int j = 0; j < 4; j++) {
            int4 v = wi[j];
            o[j * 4 + 0] = (int8_t)v.x; o[j * 4 + 1] = (int8_t)v.y;
            o[j * 4 + 2] = (int8_t)v.z; o[j * 4 + 3] = (int8_t)v.w;
        }
    } else if (mode == 2) {
        const __nv_bfloat16* wb = (const __nv_bfloat16*)w + g * 16;
#pragma unroll
        for (int j = 0; j < 16; j++) o[j] = (int8_t)(int)__bfloat162float(wb[j]);
    } else {
        const float4* wf = (const float4*)w + g * 4;
#pragma unroll
        for (int j = 0; j < 4; j++) {
            float4 v = wf[j];
            o[j * 4 + 0] = (int8_t)(int)v.x; o[j * 4 + 1] = (int8_t)(int)v.y;
            o[j * 4 + 2] = (int8_t)(int)v.z; o[j * 4 + 3] = (int8_t)(int)v.w;
        }
    }
    *(int4*)(g_w8 + g * 16) = *(int4*)o;
}

// ---------------------------------------------------------------------------
// Kernel 1: per-token dynamic quantization (matches JAX: rint half-even, rn div)
// ---------------------------------------------------------------------------
__device__ __forceinline__ int q8(float x, float s) {
    float r = rintf(__fdiv_rn(x, s));
    r = fminf(fmaxf(r, -128.0f), 127.0f);
    return (int)r;
}

__global__ void __launch_bounds__(256) quant_kernel(const float* __restrict__ x) {
    int t = blockIdx.x;
    int tid = threadIdx.x;
    const float4* xr = (const float4*)(x + (size_t)t * KDIM);
    float4 v[4];
    float am = 0.0f;
#pragma unroll
    for (int i = 0; i < 4; i++) {
        v[i] = xr[tid * 4 + i];
        am = fmaxf(am, fmaxf(fmaxf(fabsf(v[i].x), fabsf(v[i].y)),
                             fmaxf(fabsf(v[i].z), fabsf(v[i].w))));
    }
    __shared__ float red[256];
    red[tid] = am;
    __syncthreads();
    for (int s = 128; s > 0; s >>= 1) {
        if (tid < s) red[tid] = fmaxf(red[tid], red[tid + s]);
        __syncthreads();
    }
    float s = fmaxf(__fdiv_rn(red[0], 127.0f), 1e-8f);
    if (tid == 0) g_ascale[t] = s;

    uint32_t p[4];
#pragma unroll
    for (int i = 0; i < 4; i++) {
        int a0 = q8(v[i].x, s), a1 = q8(v[i].y, s), a2 = q8(v[i].z, s), a3 = q8(v[i].w, s);
        p[i] = (uint32_t)(a0 & 255) | ((uint32_t)(a1 & 255) << 8) |
               ((uint32_t)(a2 & 255) << 16) | ((uint32_t)(a3 & 255) << 24);
    }
    ((int4*)(g_xq + (size_t)t * KDIM))[tid] =
        make_int4((int)p[0], (int)p[1], (int)p[2], (int)p[3]);
}

// ---------------------------------------------------------------------------
// Kernel 2: IMMA GEMM + dequant epilogue
// ---------------------------------------------------------------------------
__device__ __forceinline__ void copy_chunk(int m0, int n0, int c, int stage,
                                           uint32_t sb, int tid) {
    uint32_t st = sb + SM_AB + stage * STAGE_BYTES;
    const int8_t* asrc = g_xq + (size_t)m0 * KDIM + (size_t)c * KCH;
#pragma unroll
    for (int i = 0; i < 2; i++) {
        int idx = tid + i * 512;
        int row = idx >> 3, u = idx & 7;
        cp16(st + row * ROWB + u * 16, asrc + (size_t)row * KDIM + u * 16);
    }
    const int8_t* bsrc = g_w8 + (size_t)n0 * KDIM + (size_t)c * KCH;
    uint32_t bb = st + A_BYTES;
#pragma unroll
    for (int i = 0; i < 4; i++) {
        int idx = tid + i * 512;
        int row = idx >> 3, u = idx & 7;
        cp16(bb + row * ROWB + u * 16, bsrc + (size_t)row * KDIM + u * 16);
    }
}

__global__ void __launch_bounds__(512, 1) gemm_kernel(const float* __restrict__ wscale,
                                                      const float* __restrict__ bias,
                                                      float* __restrict__ out) {
    extern __shared__ char smem[];
    uint32_t sb = smem_u32(smem);
    int tid = threadIdx.x;
    int wid = tid >> 5;
    int lane = tid & 31;
    int m0 = blockIdx.y * TILE_M;
    int n0 = blockIdx.x * TILE_N;

    int wm = wid & 3;
    int wn = wid >> 2;
    int g4 = lane >> 2;
    int tg = lane & 3;

    float* smem_ws = (float*)(smem + SM_WS);
    float* smem_bs = (float*)(smem + SM_BS);
    if (tid < 256)      smem_ws[tid] = wscale[n0 + tid];
    else                smem_bs[tid - 256] = bias[n0 + tid - 256];

    uint32_t a_base = (uint32_t)((wm * 32 + g4) * ROWB + tg * 4);
    uint32_t b_base = (uint32_t)(A_BYTES + (wn * 64 + g4) * ROWB + tg * 4);

    int acc[2][8][4];
#pragma unroll
    for (int f = 0; f < 2; f++)
#pragma unroll
        for (int nf = 0; nf < 8; nf++)
#pragma unroll
            for (int i = 0; i < 4; i++) acc[f][nf][i] = 0;

    copy_chunk(m0, n0, 0, 0, sb, tid);
    asm volatile("cp.async.commit_group;" ::: "memory");
    copy_chunk(m0, n0, 1, 1, sb, tid);
    asm volatile("cp.async.commit_group;" ::: "memory");

    for (int c = 0; c < NCHUNK; c++) {
        if (c + 2 < NCHUNK) {
            copy_chunk(m0, n0, c + 2, (c + 2) % NSTAGE, sb, tid);
            asm volatile("cp.async.commit_group;" ::: "memory");
        }
        if (c <= NCHUNK - 3)      asm volatile("cp.async.wait_group 2;" ::: "memory");
        else if (c == NCHUNK - 2) asm volatile("cp.async.wait_group 1;" ::: "memory");
        else                      asm volatile("cp.async.wait_group 0;" ::: "memory");
        __syncthreads();

        uint32_t st = sb + SM_AB + (c % NSTAGE) * STAGE_BYTES;
#pragma unroll
        for (int ks = 0; ks < 8; ks++) {
            uint32_t koff = ks * 16;
            uint32_t a0[2], a1[2];
#pragma unroll
            for (int f = 0; f < 2; f++) {
                uint32_t ab = st + a_base + f * (16 * ROWB) + koff;
                a0[f] = lds32(ab);
                a1[f] = lds32(ab + 8 * ROWB);
            }
#pragma unroll
            for (int q = 0; q < 4; q++) {
#pragma unroll
                for (int h = 0; h < 2; h++) {
                    uint32_t b0 = lds32(st + b_base + (q * 16 + h * 8) * ROWB + koff);
#pragma unroll
                    for (int f = 0; f < 2; f++)
                        mma_s8_k16(acc[f][2 * q + h], a0[f], a1[f], b0);
                }
            }
        }
        __syncthreads();
    }

    // ---- epilogue: dequant + direct float2 stores ----
#pragma unroll
    for (int f = 0; f < 2; f++) {
        int mA = m0 + wm * 32 + f * 16 + g4;
        float as0 = g_ascale[mA];
        float as1 = g_ascale[mA + 8];
#pragma unroll
        for (int nf = 0; nf < 8; nf++) {
            int col = wn * 64 + nf * 8 + tg * 2;
            float ws0 = smem_ws[col],     ws1 = smem_ws[col + 1];
            float bs0 = smem_bs[col],     bs1 = smem_bs[col + 1];
            float2 v0, v1;
            v0.x = fmaf((float)acc[f][nf][0] * as0, ws0, bs0);
            v0.y = fmaf((float)acc[f][nf][1] * as0, ws1, bs1);
            v1.x = fmaf((float)acc[f][nf][2] * as1, ws0, bs0);
            v1.y = fmaf((float)acc[f][nf][3] * as1, ws1, bs1);
            *(float2*)(out + (size_t)mA * NDIM + n0 + col) = v0;
            *(float2*)(out + (size_t)(mA + 8) * NDIM + n0 + col) = v1;
        }
    }
}

// ---------------------------------------------------------------------------
extern "C" void kernel_launch(void* const* d_in, const int* in_sizes, int n_in,
                              void* d_out, int out_size) {
    // Input order: dict (x, weight, weight_scale, bias) confirmed by round-3
    // invariance, but keep the alphabetical guard (weight/ws at 1/2 either way).
    const float* x;
    const float* bs;
    if (in_sizes[0] == NDIM) {           // alphabetical: bias first
        bs = (const float*)d_in[0];
        x  = (const float*)d_in[3];
    } else {                             // dict order: x first
        x  = (const float*)d_in[0];
        bs = (const float*)d_in[3];
    }
    const void*  w  = d_in[1];
    const float* ws = (const float*)d_in[2];
    float* out = (float*)d_out;

    cudaFuncSetAttribute(gemm_kernel, cudaFuncAttributeMaxDynamicSharedMemorySize, SMEM_TOTAL);

    detect_kernel<<<1, 256>>>(w);
    pack_kernel<<<(int)((W_ELEMS / 16 + 255) / 256), 256>>>(w);   // 12288 blocks
    quant_kernel<<<TOK, 256>>>(x);
    dim3 grid(NDIM / TILE_N, TOK / TILE_M);   // (48, 32)
    gemm_kernel<<<grid, 512, SMEM_TOTAL>>>(ws, bs, out);
}

// round 5
// speedup vs baseline: 1.1643x; 1.1643x over previous
#include <cuda_runtime.h>
#include <cuda_bf16.h>
#include <cstdint>

// ---------------------------------------------------------------------------
// W8A8 dynamic-quant linear:  y = (q8(x) @ W^T) * act_scale * w_scale + bias
// TOK=4096, K=4096, OUT(N)=12288
//
// Round 5: round 4 passed (5970 us) and ncu shows pure tensor-pipe
// instruction-throughput bound (tensor=88%, issue=9%, DRAM<1%). Halve the
// IMMA instruction count: m16n8k16 -> m16n8k32 (4096 MACs/instr) with
// ldmatrix.x4 operand loads (layout proven correct by rounds 2/3 bit-identical
// results). Everything else unchanged.
// ---------------------------------------------------------------------------

#define TOK   4096
#define KDIM  4096
#define NDIM  12288

#define TILE_M 128
#define TILE_N 256
#define KCH    128
#define NCHUNK (KDIM / KCH)      // 32
#define NSTAGE 3

#define ROWB   144               // 128 B K-chunk + 16 B pad
#define A_BYTES (TILE_M * ROWB)  // 18432
#define B_BYTES (TILE_N * ROWB)  // 36864
#define STAGE_BYTES (A_BYTES + B_BYTES)   // 55296

// SMEM layout (bytes)
#define SM_WS 0                  // 256 floats
#define SM_BS 1024               // 256 floats
#define SM_AB 2048               // NSTAGE stages
#define SMEM_TOTAL (SM_AB + NSTAGE * STAGE_BYTES)   // 167936

#define W_ELEMS ((size_t)NDIM * KDIM)    // 50331648

// Scratch (module globals -- allocation-free per harness rules)
__device__ int8_t g_xq[(size_t)TOK * KDIM];
__device__ int8_t g_w8[W_ELEMS];
__device__ float  g_ascale[TOK];
__device__ int    g_wmode;       // 0=int8 raw, 1=int32, 2=bf16, 3=f32

// ---------------------------------------------------------------------------
__device__ __forceinline__ uint32_t smem_u32(const void* p) {
    uint32_t a;
    asm("{ .reg .u64 t; cvta.to.shared.u64 t, %1; cvt.u32.u64 %0, t; }" : "=r"(a) : "l"(p));
    return a;
}

__device__ __forceinline__ void cp16(uint32_t dst, const void* src) {
    asm volatile("cp.async.cg.shared.global [%0], [%1], 16;" :: "r"(dst), "l"(src));
}

__device__ __forceinline__ void ldsm_x4(uint32_t* r, uint32_t addr) {
    asm volatile("ldmatrix.sync.aligned.m8n8.x4.shared.b16 {%0,%1,%2,%3}, [%4];"
                 : "=r"(r[0]), "=r"(r[1]), "=r"(r[2]), "=r"(r[3]) : "r"(addr));
}

__device__ __forceinline__ void mma_s8_k32(int* c, const uint32_t* a, uint32_t b0, uint32_t b1) {
    asm volatile(
        "mma.sync.aligned.m16n8k32.row.col.s32.s8.s8.s32 "
        "{%0,%1,%2,%3}, {%4,%5,%6,%7}, {%8,%9}, {%0,%1,%2,%3};"
        : "+r"(c[0]), "+r"(c[1]), "+r"(c[2]), "+r"(c[3])
        : "r"(a[0]), "r"(a[1]), "r"(a[2]), "r"(a[3]), "r"(b0), "r"(b1));
}

// ---------------------------------------------------------------------------
// Weight format autodetect + repack (proven necessary in round 4)
// ---------------------------------------------------------------------------
__global__ void detect_kernel(const void* w) {
    __shared__ int ok32, okf32, okbf;
    int tid = threadIdx.x;
    if (tid == 0) { ok32 = 1; okf32 = 1; okbf = 1; }
    __syncthreads();
    const int*            wi = (const int*)w;
    const float*          wf = (const float*)w;
    const __nv_bfloat16*  wb = (const __nv_bfloat16*)w;
#pragma unroll
    for (int i = 0; i < 4; i++) {
        int idx = tid * 4 + i;
        int v = wi[idx];
        if (v < -128 || v > 127) ok32 = 0;
        float f = wf[idx];
        if (!(f == rintf(f)) || f < -128.0f || f > 127.0f) okf32 = 0;
        float b = __bfloat162float(wb[idx]);
        if (!(b == rintf(b)) || b < -128.0f || b > 127.0f) okbf = 0;
    }
    __syncthreads();
    if (tid == 0)
        g_wmode = ok32 ? 1 : (okf32 ? 3 : (okbf ? 2 : 0));
}

__global__ void __launch_bounds__(256) pack_kernel(const void* w) {
    size_t g = (size_t)blockIdx.x * blockDim.x + threadIdx.x;
    if (g * 16 >= W_ELEMS) return;
    int mode = g_wmode;
    int8_t o[16];
    if (mode == 0) {
        *(int4*)o = ((const int4*)w)[g];
    } else if (mode == 1) {
        const int4* wi = (const int4*)w + g * 4;
#pragma unroll
        for (int j = 0; j < 4; j++) {
            int4 v = wi[j];
            o[j * 4 + 0] = (int8_t)v.x; o[j * 4 + 1] = (int8_t)v.y;
            o[j * 4 + 2] = (int8_t)v.z; o[j * 4 + 3] = (int8_t)v.w;
        }
    } else if (mode == 2) {
        const __nv_bfloat16* wb = (const __nv_bfloat16*)w + g * 16;
#pragma unroll
        for (int j = 0; j < 16; j++) o[j] = (int8_t)(int)__bfloat162float(wb[j]);
    } else {
        const float4* wf = (const float4*)w + g * 4;
#pragma unroll
        for (int j = 0; j < 4; j++) {
            float4 v = wf[j];
            o[j * 4 + 0] = (int8_t)(int)v.x; o[j * 4 + 1] = (int8_t)(int)v.y;
            o[j * 4 + 2] = (int8_t)(int)v.z; o[j * 4 + 3] = (int8_t)(int)v.w;
        }
    }
    *(int4*)(g_w8 + g * 16) = *(int4*)o;
}

// ---------------------------------------------------------------------------
// Kernel 1: per-token dynamic quantization
// ---------------------------------------------------------------------------
__device__ __forceinline__ int q8(float x, float s) {
    float r = rintf(__fdiv_rn(x, s));
    r = fminf(fmaxf(r, -128.0f), 127.0f);
    return (int)r;
}

__global__ void __launch_bounds__(256) quant_kernel(const float* __restrict__ x) {
    int t = blockIdx.x;
    int tid = threadIdx.x;
    const float4* xr = (const float4*)(x + (size_t)t * KDIM);
    float4 v[4];
    float am = 0.0f;
#pragma unroll
    for (int i = 0; i < 4; i++) {
        v[i] = xr[tid * 4 + i];
        am = fmaxf(am, fmaxf(fmaxf(fabsf(v[i].x), fabsf(v[i].y)),
                             fmaxf(fabsf(v[i].z), fabsf(v[i].w))));
    }
    __shared__ float red[256];
    red[tid] = am;
    __syncthreads();
    for (int s = 128; s > 0; s >>= 1) {
        if (tid < s) red[tid] = fmaxf(red[tid], red[tid + s]);
        __syncthreads();
    }
    float s = fmaxf(__fdiv_rn(red[0], 127.0f), 1e-8f);
    if (tid == 0) g_ascale[t] = s;

    uint32_t p[4];
#pragma unroll
    for (int i = 0; i < 4; i++) {
        int a0 = q8(v[i].x, s), a1 = q8(v[i].y, s), a2 = q8(v[i].z, s), a3 = q8(v[i].w, s);
        p[i] = (uint32_t)(a0 & 255) | ((uint32_t)(a1 & 255) << 8) |
               ((uint32_t)(a2 & 255) << 16) | ((uint32_t)(a3 & 255) << 24);
    }
    ((int4*)(g_xq + (size_t)t * KDIM))[tid] =
        make_int4((int)p[0], (int)p[1], (int)p[2], (int)p[3]);
}

// ---------------------------------------------------------------------------
// Kernel 2: IMMA k32 GEMM + dequant epilogue
// ---------------------------------------------------------------------------
__device__ __forceinline__ void copy_chunk(int m0, int n0, int c, int stage,
                                           uint32_t sb, int tid) {
    uint32_t st = sb + SM_AB + stage * STAGE_BYTES;
    const int8_t* asrc = g_xq + (size_t)m0 * KDIM + (size_t)c * KCH;
#pragma unroll
    for (int i = 0; i < 2; i++) {
        int idx = tid + i * 512;
        int row = idx >> 3, u = idx & 7;
        cp16(st + row * ROWB + u * 16, asrc + (size_t)row * KDIM + u * 16);
    }
    const int8_t* bsrc = g_w8 + (size_t)n0 * KDIM + (size_t)c * KCH;
    uint32_t bb = st + A_BYTES;
#pragma unroll
    for (int i = 0; i < 4; i++) {
        int idx = tid + i * 512;
        int row = idx >> 3, u = idx & 7;
        cp16(bb + row * ROWB + u * 16, bsrc + (size_t)row * KDIM + u * 16);
    }
}

__global__ void __launch_bounds__(512, 1) gemm_kernel(const float* __restrict__ wscale,
                                                      const float* __restrict__ bias,
                                                      float* __restrict__ out) {
    extern __shared__ char smem[];
    uint32_t sb = smem_u32(smem);
    int tid = threadIdx.x;
    int wid = tid >> 5;
    int lane = tid & 31;
    int m0 = blockIdx.y * TILE_M;
    int n0 = blockIdx.x * TILE_N;

    int wm = wid & 3;            // 4 M-strips of 32
    int wn = wid >> 2;           // 4 N-strips of 64

    float* smem_ws = (float*)(smem + SM_WS);
    float* smem_bs = (float*)(smem + SM_BS);
    if (tid < 256)      smem_ws[tid] = wscale[n0 + tid];
    else                smem_bs[tid - 256] = bias[n0 + tid - 256];

    // ldmatrix per-lane offsets (within a stage):
    // A (x4): tiles {rows+0 k0-15, rows+8 k0-15, rows+0 k16-31, rows+8 k16-31}
    int g = lane >> 3, lr = lane & 7;
    uint32_t aoff = (uint32_t)((wm * 32 + (g & 1) * 8 + lr) * ROWB + (g >> 1) * 16);
    // B (x4): tiles {nf+0 k0-15, nf+0 k16-31, nf+8 k0-15, nf+8 k16-31}
    uint32_t boff = (uint32_t)(A_BYTES + (wn * 64 + (g >> 1) * 8 + lr) * ROWB + (g & 1) * 16);

    int acc[2][8][4];
#pragma unroll
    for (int f = 0; f < 2; f++)
#pragma unroll
        for (int nf = 0; nf < 8; nf++)
#pragma unroll
            for (int i = 0; i < 4; i++) acc[f][nf][i] = 0;

    copy_chunk(m0, n0, 0, 0, sb, tid);
    asm volatile("cp.async.commit_group;" ::: "memory");
    copy_chunk(m0, n0, 1, 1, sb, tid);
    asm volatile("cp.async.commit_group;" ::: "memory");

    for (int c = 0; c < NCHUNK; c++) {
        if (c + 2 < NCHUNK) {
            copy_chunk(m0, n0, c + 2, (c + 2) % NSTAGE, sb, tid);
            asm volatile("cp.async.commit_group;" ::: "memory");
        }
        if (c <= NCHUNK - 3)      asm volatile("cp.async.wait_group 2;" ::: "memory");
        else if (c == NCHUNK - 2) asm volatile("cp.async.wait_group 1;" ::: "memory");
        else                      asm volatile("cp.async.wait_group 0;" ::: "memory");
        __syncthreads();

        uint32_t st = sb + SM_AB + (c % NSTAGE) * STAGE_BYTES;
#pragma unroll
        for (int ks = 0; ks < 4; ks++) {          // 4 x k32 per 128-B chunk
            uint32_t a[2][4];
#pragma unroll
            for (int f = 0; f < 2; f++)
                ldsm_x4(a[f], st + aoff + f * (16 * ROWB) + ks * 32);
            uint32_t b[4][4];
#pragma unroll
            for (int q = 0; q < 4; q++)
                ldsm_x4(b[q], st + boff + q * (16 * ROWB) + ks * 32);
#pragma unroll
            for (int f = 0; f < 2; f++)
#pragma unroll
                for (int q = 0; q < 4; q++) {
                    mma_s8_k32(acc[f][2 * q],     a[f], b[q][0], b[q][1]);
                    mma_s8_k32(acc[f][2 * q + 1], a[f], b[q][2], b[q][3]);
                }
        }
        __syncthreads();
    }

    // ---- epilogue: dequant + direct float2 stores ----
    int lrow = lane >> 2;
    int lcol2 = (lane & 3) * 2;
#pragma unroll
    for (int f = 0; f < 2; f++) {
        int mA = m0 + wm * 32 + f * 16 + lrow;
        float as0 = g_ascale[mA];
        float as1 = g_ascale[mA + 8];
#pragma unroll
        for (int nf = 0; nf < 8; nf++) {
            int col = wn * 64 + nf * 8 + lcol2;
            float ws0 = smem_ws[col],     ws1 = smem_ws[col + 1];
            float bs0 = smem_bs[col],     bs1 = smem_bs[col + 1];
            float2 v0, v1;
            v0.x = fmaf((float)acc[f][nf][0] * as0, ws0, bs0);
            v0.y = fmaf((float)acc[f][nf][1] * as0, ws1, bs1);
            v1.x = fmaf((float)acc[f][nf][2] * as1, ws0, bs0);
            v1.y = fmaf((float)acc[f][nf][3] * as1, ws1, bs1);
            *(float2*)(out + (size_t)mA * NDIM + n0 + col) = v0;
            *(float2*)(out + (size_t)(mA + 8) * NDIM + n0 + col) = v1;
        }
    }
}

// ---------------------------------------------------------------------------
extern "C" void kernel_launch(void* const* d_in, const int* in_sizes, int n_in,
                              void* d_out, int out_size) {
    const float* x;
    const float* bs;
    if (in_sizes[0] == NDIM) {           // alphabetical: bias first
        bs = (const float*)d_in[0];
        x  = (const float*)d_in[3];
    } else {                             // dict order: x first
        x  = (const float*)d_in[0];
        bs = (const float*)d_in[3];
    }
    const void*  w  = d_in[1];
    const float* ws = (const float*)d_in[2];
    float* out = (float*)d_out;

    cudaFuncSetAttribute(gemm_kernel, cudaFuncAttributeMaxDynamicSharedMemorySize, SMEM_TOTAL);

    detect_kernel<<<1, 256>>>(w);
    pack_kernel<<<(int)((W_ELEMS / 16 + 255) / 256), 256>>>(w);
    quant_kernel<<<TOK, 256>>>(x);
    dim3 grid(NDIM / TILE_N, TOK / TILE_M);   // (48, 32)
    gemm_kernel<<<grid, 512, SMEM_TOTAL>>>(ws, bs, out);
}

// round 6
// speedup vs baseline: 2.4178x; 2.0765x over previous
#include <cuda_runtime.h>
#include <cuda_bf16.h>
#include <cstdint>

// ---------------------------------------------------------------------------
// W8A8 dynamic-quant linear:  y = (q8(x) @ W^T) * act_scale * w_scale + bias
// TOK=4096, K=4096, OUT(N)=12288
//
// Round 6 A/B experiment: legacy IMMA measured at ~150 MACs/cyc/SM (emulated).
// Question: is legacy bf16 HMMA native-speed? Split N:
//   rows [0,6144):     bf16 HMMA m16n8k16 GEMM (operands exact in bf16)
//   rows [6144,12288): proven IMMA m16n8k32 GEMM (round 5)
// ncu reports both GEMM durations separately -> per-engine measurement.
// ---------------------------------------------------------------------------

#define TOK   4096
#define KDIM  4096
#define NDIM  12288
#define NHALF 6144

#define TILE_M 128
#define TILE_N 256
#define NSTAGE 3

#define ROWB   144               // 128 B K-chunk + 16 B pad
#define A_BYTES (TILE_M * ROWB)  // 18432
#define B_BYTES (TILE_N * ROWB)  // 36864
#define STAGE_BYTES (A_BYTES + B_BYTES)   // 55296

// SMEM layout (bytes)
#define SM_WS 0                  // 256 floats
#define SM_BS 1024               // 256 floats
#define SM_AB 2048               // NSTAGE stages
#define SMEM_TOTAL (SM_AB + NSTAGE * STAGE_BYTES)   // 167936

#define W_ELEMS ((size_t)NDIM * KDIM)    // 50331648

// Scratch (module globals -- allocation-free per harness rules)
__device__ int8_t        g_xq[(size_t)TOK * KDIM];
__device__ __nv_bfloat16 g_xbf[(size_t)TOK * KDIM];
__device__ int8_t        g_w8[W_ELEMS];
__device__ __nv_bfloat16 g_wbf[(size_t)NHALF * KDIM];
__device__ float         g_ascale[TOK];
__device__ int           g_wmode;   // 0=int8 raw, 1=int32, 2=bf16, 3=f32

// ---------------------------------------------------------------------------
__device__ __forceinline__ uint32_t smem_u32(const void* p) {
    uint32_t a;
    asm("{ .reg .u64 t; cvta.to.shared.u64 t, %1; cvt.u32.u64 %0, t; }" : "=r"(a) : "l"(p));
    return a;
}

__device__ __forceinline__ void cp16(uint32_t dst, const void* src) {
    asm volatile("cp.async.cg.shared.global [%0], [%1], 16;" :: "r"(dst), "l"(src));
}

__device__ __forceinline__ void ldsm_x4(uint32_t* r, uint32_t addr) {
    asm volatile("ldmatrix.sync.aligned.m8n8.x4.shared.b16 {%0,%1,%2,%3}, [%4];"
                 : "=r"(r[0]), "=r"(r[1]), "=r"(r[2]), "=r"(r[3]) : "r"(addr));
}

__device__ __forceinline__ void mma_s8_k32(int* c, const uint32_t* a, uint32_t b0, uint32_t b1) {
    asm volatile(
        "mma.sync.aligned.m16n8k32.row.col.s32.s8.s8.s32 "
        "{%0,%1,%2,%3}, {%4,%5,%6,%7}, {%8,%9}, {%0,%1,%2,%3};"
        : "+r"(c[0]), "+r"(c[1]), "+r"(c[2]), "+r"(c[3])
        : "r"(a[0]), "r"(a[1]), "r"(a[2]), "r"(a[3]), "r"(b0), "r"(b1));
}

__device__ __forceinline__ void mma_bf16_k16(float* c, const uint32_t* a, uint32_t b0, uint32_t b1) {
    asm volatile(
        "mma.sync.aligned.m16n8k16.row.col.f32.bf16.bf16.f32 "
        "{%0,%1,%2,%3}, {%4,%5,%6,%7}, {%8,%9}, {%0,%1,%2,%3};"
        : "+f"(c[0]), "+f"(c[1]), "+f"(c[2]), "+f"(c[3])
        : "r"(a[0]), "r"(a[1]), "r"(a[2]), "r"(a[3]), "r"(b0), "r"(b1));
}

// ---------------------------------------------------------------------------
// Weight format autodetect + repack (proven in round 4)
// ---------------------------------------------------------------------------
__global__ void detect_kernel(const void* w) {
    __shared__ int ok32, okf32, okbf;
    int tid = threadIdx.x;
    if (tid == 0) { ok32 = 1; okf32 = 1; okbf = 1; }
    __syncthreads();
    const int*            wi = (const int*)w;
    const float*          wf = (const float*)w;
    const __nv_bfloat16*  wb = (const __nv_bfloat16*)w;
#pragma unroll
    for (int i = 0; i < 4; i++) {
        int idx = tid * 4 + i;
        int v = wi[idx];
        if (v < -128 || v > 127) ok32 = 0;
        float f = wf[idx];
        if (!(f == rintf(f)) || f < -128.0f || f > 127.0f) okf32 = 0;
        float b = __bfloat162float(wb[idx]);
        if (!(b == rintf(b)) || b < -128.0f || b > 127.0f) okbf = 0;
    }
    __syncthreads();
    if (tid == 0)
        g_wmode = ok32 ? 1 : (okf32 ? 3 : (okbf ? 2 : 0));
}

__global__ void __launch_bounds__(256) pack_kernel(const void* w) {
    size_t g = (size_t)blockIdx.x * blockDim.x + threadIdx.x;
    if (g * 16 >= W_ELEMS) return;
    int mode = g_wmode;
    int8_t o[16];
    if (mode == 0) {
        *(int4*)o = ((const int4*)w)[g];
    } else if (mode == 1) {
        const int4* wi = (const int4*)w + g * 4;
#pragma unroll
        for (int j = 0; j < 4; j++) {
            int4 v = wi[j];
            o[j * 4 + 0] = (int8_t)v.x; o[j * 4 + 1] = (int8_t)v.y;
            o[j * 4 + 2] = (int8_t)v.z; o[j * 4 + 3] = (int8_t)v.w;
        }
    } else if (mode == 2) {
        const __nv_bfloat16* wb = (const __nv_bfloat16*)w + g * 16;
#pragma unroll
        for (int j = 0; j < 16; j++) o[j] = (int8_t)(int)__bfloat162float(wb[j]);
    } else {
        const float4* wf = (const float4*)w + g * 4;
#pragma unroll
        for (int j = 0; j < 4; j++) {
            float4 v = wf[j];
            o[j * 4 + 0] = (int8_t)(int)v.x; o[j * 4 + 1] = (int8_t)(int)v.y;
            o[j * 4 + 2] = (int8_t)(int)v.z; o[j * 4 + 3] = (int8_t)(int)v.w;
        }
    }
    *(int4*)(g_w8 + g * 16) = *(int4*)o;
}

// Convert first NHALF rows of canonical int8 weight to bf16 (for HMMA half)
__global__ void __launch_bounds__(256) packbf_kernel() {
    size_t g = (size_t)blockIdx.x * blockDim.x + threadIdx.x;   // 16 elems each
    if (g * 16 >= (size_t)NHALF * KDIM) return;
    int8_t b[16];
    *(int4*)b = *(const int4*)(g_w8 + g * 16);
    uint32_t o[8];
#pragma unroll
    for (int j = 0; j < 8; j++) {
        __nv_bfloat162 h = __floats2bfloat162_rn((float)b[2 * j], (float)b[2 * j + 1]);
        o[j] = *(uint32_t*)&h;
    }
    uint4* dst = (uint4*)(g_wbf + g * 16);
    dst[0] = make_uint4(o[0], o[1], o[2], o[3]);
    dst[1] = make_uint4(o[4], o[5], o[6], o[7]);
}

// ---------------------------------------------------------------------------
// Kernel 1: per-token dynamic quantization -> int8 AND bf16 copies
// ---------------------------------------------------------------------------
__device__ __forceinline__ int q8(float x, float s) {
    float r = rintf(__fdiv_rn(x, s));
    r = fminf(fmaxf(r, -128.0f), 127.0f);
    return (int)r;
}

__global__ void __launch_bounds__(256) quant_kernel(const float* __restrict__ x) {
    int t = blockIdx.x;
    int tid = threadIdx.x;
    const float4* xr = (const float4*)(x + (size_t)t * KDIM);
    float4 v[4];
    float am = 0.0f;
#pragma unroll
    for (int i = 0; i < 4; i++) {
        v[i] = xr[tid * 4 + i];
        am = fmaxf(am, fmaxf(fmaxf(fabsf(v[i].x), fabsf(v[i].y)),
                             fmaxf(fabsf(v[i].z), fabsf(v[i].w))));
    }
    __shared__ float red[256];
    red[tid] = am;
    __syncthreads();
    for (int s = 128; s > 0; s >>= 1) {
        if (tid < s) red[tid] = fmaxf(red[tid], red[tid + s]);
        __syncthreads();
    }
    float s = fmaxf(__fdiv_rn(red[0], 127.0f), 1e-8f);
    if (tid == 0) g_ascale[t] = s;

    int q[16];
    q[0] = q8(v[0].x, s); q[1] = q8(v[0].y, s); q[2] = q8(v[0].z, s); q[3] = q8(v[0].w, s);
    q[4] = q8(v[1].x, s); q[5] = q8(v[1].y, s); q[6] = q8(v[1].z, s); q[7] = q8(v[1].w, s);
    q[8] = q8(v[2].x, s); q[9] = q8(v[2].y, s); q[10] = q8(v[2].z, s); q[11] = q8(v[2].w, s);
    q[12] = q8(v[3].x, s); q[13] = q8(v[3].y, s); q[14] = q8(v[3].z, s); q[15] = q8(v[3].w, s);

    uint32_t p[4];
#pragma unroll
    for (int i = 0; i < 4; i++)
        p[i] = (uint32_t)(q[4 * i] & 255) | ((uint32_t)(q[4 * i + 1] & 255) << 8) |
               ((uint32_t)(q[4 * i + 2] & 255) << 16) | ((uint32_t)(q[4 * i + 3] & 255) << 24);
    ((int4*)(g_xq + (size_t)t * KDIM))[tid] =
        make_int4((int)p[0], (int)p[1], (int)p[2], (int)p[3]);

    uint32_t h[8];
#pragma unroll
    for (int j = 0; j < 8; j++) {
        __nv_bfloat162 hb = __floats2bfloat162_rn((float)q[2 * j], (float)q[2 * j + 1]);
        h[j] = *(uint32_t*)&hb;
    }
    uint4* dst = (uint4*)(g_xbf + (size_t)t * KDIM + tid * 16);
    dst[0] = make_uint4(h[0], h[1], h[2], h[3]);
    dst[1] = make_uint4(h[4], h[5], h[6], h[7]);
}

// ---------------------------------------------------------------------------
// Shared GEMM copy helper: A/B tiles, 128-B rows per chunk into ROWB-144 smem
// ---------------------------------------------------------------------------
template <typename TA, typename TB>
__device__ __forceinline__ void copy_chunk_t(const TA* abase_g, const TB* bbase_g,
                                             int c, int stage, uint32_t sb, int tid) {
    // A tile: 128 rows x 128 B  (1024 cp16 / 512 thr = 2 each)
    uint32_t st = sb + SM_AB + stage * STAGE_BYTES;
    const char* asrc = (const char*)abase_g + (size_t)c * 128;
#pragma unroll
    for (int i = 0; i < 2; i++) {
        int idx = tid + i * 512;
        int row = idx >> 3, u = idx & 7;
        cp16(st + row * ROWB + u * 16, asrc + (size_t)row * (KDIM * sizeof(TA)) + u * 16);
    }
    // B tile: 256 rows x 128 B  (2048 cp16 / 512 thr = 4 each)
    const char* bsrc = (const char*)bbase_g + (size_t)c * 128;
    uint32_t bb = st + A_BYTES;
#pragma unroll
    for (int i = 0; i < 4; i++) {
        int idx = tid + i * 512;
        int row = idx >> 3, u = idx & 7;
        cp16(bb + row * ROWB + u * 16, bsrc + (size_t)row * (KDIM * sizeof(TB)) + u * 16);
    }
}

// ---------------------------------------------------------------------------
// GEMM kernels. Identical structure; differ in operand type + MMA.
// NCH = number of 128-B K-chunks (32 for int8, 64 for bf16).
// ---------------------------------------------------------------------------
__global__ void __launch_bounds__(512, 1) imma_gemm(const float* __restrict__ wscale,
                                                    const float* __restrict__ bias,
                                                    float* __restrict__ out) {
    const int NCH = 32;
    extern __shared__ char smem[];
    uint32_t sb = smem_u32(smem);
    int tid = threadIdx.x, wid = tid >> 5, lane = tid & 31;
    int m0 = blockIdx.y * TILE_M;
    int n0 = NHALF + blockIdx.x * TILE_N;
    int wm = wid & 3, wn = wid >> 2;

    float* smem_ws = (float*)(smem + SM_WS);
    float* smem_bs = (float*)(smem + SM_BS);
    if (tid < 256)      smem_ws[tid] = wscale[n0 + tid];
    else                smem_bs[tid - 256] = bias[n0 + tid - 256];

    int g = lane >> 3, lr = lane & 7;
    uint32_t aoff = (uint32_t)((wm * 32 + (g & 1) * 8 + lr) * ROWB + (g >> 1) * 16);
    uint32_t boff = (uint32_t)(A_BYTES + (wn * 64 + (g >> 1) * 8 + lr) * ROWB + (g & 1) * 16);

    int acc[2][8][4];
#pragma unroll
    for (int f = 0; f < 2; f++)
#pragma unroll
        for (int nf = 0; nf < 8; nf++)
#pragma unroll
            for (int i = 0; i < 4; i++) acc[f][nf][i] = 0;

    const int8_t* Ag = g_xq + (size_t)m0 * KDIM;
    const int8_t* Bg = g_w8 + (size_t)n0 * KDIM;

    copy_chunk_t(Ag, Bg, 0, 0, sb, tid);
    asm volatile("cp.async.commit_group;" ::: "memory");
    copy_chunk_t(Ag, Bg, 1, 1, sb, tid);
    asm volatile("cp.async.commit_group;" ::: "memory");

    for (int c = 0; c < NCH; c++) {
        if (c + 2 < NCH) {
            copy_chunk_t(Ag, Bg, c + 2, (c + 2) % NSTAGE, sb, tid);
            asm volatile("cp.async.commit_group;" ::: "memory");
        }
        if (c <= NCH - 3)      asm volatile("cp.async.wait_group 2;" ::: "memory");
        else if (c == NCH - 2) asm volatile("cp.async.wait_group 1;" ::: "memory");
        else                   asm volatile("cp.async.wait_group 0;" ::: "memory");
        __syncthreads();

        uint32_t st = sb + SM_AB + (c % NSTAGE) * STAGE_BYTES;
#pragma unroll
        for (int ks = 0; ks < 4; ks++) {
            uint32_t a[2][4];
#pragma unroll
            for (int f = 0; f < 2; f++)
                ldsm_x4(a[f], st + aoff + f * (16 * ROWB) + ks * 32);
            uint32_t b[4][4];
#pragma unroll
            for (int q = 0; q < 4; q++)
                ldsm_x4(b[q], st + boff + q * (16 * ROWB) + ks * 32);
#pragma unroll
            for (int f = 0; f < 2; f++)
#pragma unroll
                for (int q = 0; q < 4; q++) {
                    mma_s8_k32(acc[f][2 * q],     a[f], b[q][0], b[q][1]);
                    mma_s8_k32(acc[f][2 * q + 1], a[f], b[q][2], b[q][3]);
                }
        }
        __syncthreads();
    }

    int lrow = lane >> 2, lcol2 = (lane & 3) * 2;
#pragma unroll
    for (int f = 0; f < 2; f++) {
        int mA = m0 + wm * 32 + f * 16 + lrow;
        float as0 = g_ascale[mA];
        float as1 = g_ascale[mA + 8];
#pragma unroll
        for (int nf = 0; nf < 8; nf++) {
            int col = wn * 64 + nf * 8 + lcol2;
            float ws0 = smem_ws[col], ws1 = smem_ws[col + 1];
            float bs0 = smem_bs[col], bs1 = smem_bs[col + 1];
            float2 v0, v1;
            v0.x = fmaf((float)acc[f][nf][0] * as0, ws0, bs0);
            v0.y = fmaf((float)acc[f][nf][1] * as0, ws1, bs1);
            v1.x = fmaf((float)acc[f][nf][2] * as1, ws0, bs0);
            v1.y = fmaf((float)acc[f][nf][3] * as1, ws1, bs1);
            *(float2*)(out + (size_t)mA * NDIM + n0 + col) = v0;
            *(float2*)(out + (size_t)(mA + 8) * NDIM + n0 + col) = v1;
        }
    }
}

__global__ void __launch_bounds__(512, 1) hmma_gemm(const float* __restrict__ wscale,
                                                    const float* __restrict__ bias,
                                                    float* __restrict__ out) {
    const int NCH = 64;          // 64-elem (128 B) bf16 chunks
    extern __shared__ char smem[];
    uint32_t sb = smem_u32(smem);
    int tid = threadIdx.x, wid = tid >> 5, lane = tid & 31;
    int m0 = blockIdx.y * TILE_M;
    int n0 = blockIdx.x * TILE_N;
    int wm = wid & 3, wn = wid >> 2;

    float* smem_ws = (float*)(smem + SM_WS);
    float* smem_bs = (float*)(smem + SM_BS);
    if (tid < 256)      smem_ws[tid] = wscale[n0 + tid];
    else                smem_bs[tid - 256] = bias[n0 + tid - 256];

    int g = lane >> 3, lr = lane & 7;
    uint32_t aoff = (uint32_t)((wm * 32 + (g & 1) * 8 + lr) * ROWB + (g >> 1) * 16);
    uint32_t boff = (uint32_t)(A_BYTES + (wn * 64 + (g >> 1) * 8 + lr) * ROWB + (g & 1) * 16);

    float acc[2][8][4];
#pragma unroll
    for (int f = 0; f < 2; f++)
#pragma unroll
        for (int nf = 0; nf < 8; nf++)
#pragma unroll
            for (int i = 0; i < 4; i++) acc[f][nf][i] = 0.0f;

    const __nv_bfloat16* Ag = g_xbf + (size_t)m0 * KDIM;
    const __nv_bfloat16* Bg = g_wbf + (size_t)n0 * KDIM;

    copy_chunk_t(Ag, Bg, 0, 0, sb, tid);
    asm volatile("cp.async.commit_group;" ::: "memory");
    copy_chunk_t(Ag, Bg, 1, 1, sb, tid);
    asm volatile("cp.async.commit_group;" ::: "memory");

    for (int c = 0; c < NCH; c++) {
        if (c + 2 < NCH) {
            copy_chunk_t(Ag, Bg, c + 2, (c + 2) % NSTAGE, sb, tid);
            asm volatile("cp.async.commit_group;" ::: "memory");
        }
        if (c <= NCH - 3)      asm volatile("cp.async.wait_group 2;" ::: "memory");
        else if (c == NCH - 2) asm volatile("cp.async.wait_group 1;" ::: "memory");
        else                   asm volatile("cp.async.wait_group 0;" ::: "memory");
        __syncthreads();

        uint32_t st = sb + SM_AB + (c % NSTAGE) * STAGE_BYTES;
#pragma unroll
        for (int ks = 0; ks < 4; ks++) {          // 4 x k16 (32 B) per 128-B chunk
            uint32_t a[2][4];
#pragma unroll
            for (int f = 0; f < 2; f++)
                ldsm_x4(a[f], st + aoff + f * (16 * ROWB) + ks * 32);
            uint32_t b[4][4];
#pragma unroll
            for (int q = 0; q < 4; q++)
                ldsm_x4(b[q], st + boff + q * (16 * ROWB) + ks * 32);
#pragma unroll
            for (int f = 0; f < 2; f++)
#pragma unroll
                for (int q = 0; q < 4; q++) {
                    mma_bf16_k16(acc[f][2 * q],     a[f], b[q][0], b[q][1]);
                    mma_bf16_k16(acc[f][2 * q + 1], a[f], b[q][2], b[q][3]);
                }
        }
        __syncthreads();
    }

    int lrow = lane >> 2, lcol2 = (lane & 3) * 2;
#pragma unroll
    for (int f = 0; f < 2; f++) {
        int mA = m0 + wm * 32 + f * 16 + lrow;
        float as0 = g_ascale[mA];
        float as1 = g_ascale[mA + 8];
#pragma unroll
        for (int nf = 0; nf < 8; nf++) {
            int col = wn * 64 + nf * 8 + lcol2;
            float ws0 = smem_ws[col], ws1 = smem_ws[col + 1];
            float bs0 = smem_bs[col], bs1 = smem_bs[col + 1];
            float2 v0, v1;
            v0.x = fmaf(acc[f][nf][0] * as0, ws0, bs0);
            v0.y = fmaf(acc[f][nf][1] * as0, ws1, bs1);
            v1.x = fmaf(acc[f][nf][2] * as1, ws0, bs0);
            v1.y = fmaf(acc[f][nf][3] * as1, ws1, bs1);
            *(float2*)(out + (size_t)mA * NDIM + n0 + col) = v0;
            *(float2*)(out + (size_t)(mA + 8) * NDIM + n0 + col) = v1;
        }
    }
}

// ---------------------------------------------------------------------------
extern "C" void kernel_launch(void* const* d_in, const int* in_sizes, int n_in,
                              void* d_out, int out_size) {
    const float* x;
    const float* bs;
    if (in_sizes[0] == NDIM) {           // alphabetical: bias first
        bs = (const float*)d_in[0];
        x  = (const float*)d_in[3];
    } else {                             // dict order: x first
        x  = (const float*)d_in[0];
        bs = (const float*)d_in[3];
    }
    const void*  w  = d_in[1];
    const float* ws = (const float*)d_in[2];
    float* out = (float*)d_out;

    cudaFuncSetAttribute(imma_gemm, cudaFuncAttributeMaxDynamicSharedMemorySize, SMEM_TOTAL);
    cudaFuncSetAttribute(hmma_gemm, cudaFuncAttributeMaxDynamicSharedMemorySize, SMEM_TOTAL);

    detect_kernel<<<1, 256>>>(w);
    pack_kernel<<<(int)((W_ELEMS / 16 + 255) / 256), 256>>>(w);
    packbf_kernel<<<(int)(((size_t)NHALF * KDIM / 16 + 255) / 256), 256>>>();
    quant_kernel<<<TOK, 256>>>(x);

    dim3 grid(NHALF / TILE_N, TOK / TILE_M);   // (24, 32) each
    hmma_gemm<<<grid, 512, SMEM_TOTAL>>>(ws, bs, out);
    imma_gemm<<<grid, 512, SMEM_TOTAL>>>(ws, bs, out);
}

// round 7
// speedup vs baseline: 4.3686x; 1.8069x over previous
#include <cuda_runtime.h>
#include <cuda_bf16.h>
#include <cstdint>

// ---------------------------------------------------------------------------
// W8A8 dynamic-quant linear:  y = (q8(x) @ W^T) * act_scale * w_scale + bias
// TOK=4096, K=4096, OUT(N)=12288
//
// Round 7: A/B test proved legacy HMMA (bf16 mma.sync) is native-speed while
// legacy IMMA is emulated (~150 MACs/cyc/SM). All-HMMA build:
//   - weight packed DIRECTLY to bf16 (format autodetect from round 4)
//   - activations quantized to bf16 (int-valued, products exact in f32 accum)
//   - single bf16 m16n8k16 GEMM over full N with cp.async 3-stage pipeline
// ---------------------------------------------------------------------------

#define TOK   4096
#define KDIM  4096
#define NDIM  12288

#define TILE_M 128
#define TILE_N 256
#define NSTAGE 3
#define NCH    64                // 64-elem (128 B) bf16 K-chunks

#define ROWB   144               // 128 B K-chunk + 16 B pad
#define A_BYTES (TILE_M * ROWB)  // 18432
#define B_BYTES (TILE_N * ROWB)  // 36864
#define STAGE_BYTES (A_BYTES + B_BYTES)   // 55296

// SMEM layout (bytes)
#define SM_WS 0                  // 256 floats
#define SM_BS 1024               // 256 floats
#define SM_AB 2048               // NSTAGE stages
#define SMEM_TOTAL (SM_AB + NSTAGE * STAGE_BYTES)   // 167936

#define W_ELEMS ((size_t)NDIM * KDIM)    // 50331648

// Scratch (module globals -- allocation-free per harness rules)
__device__ __nv_bfloat16 g_xbf[(size_t)TOK * KDIM];    // 33.5 MB
__device__ __nv_bfloat16 g_wbf[W_ELEMS];               // 100 MB
__device__ float         g_ascale[TOK];
__device__ int           g_wmode;   // 0=int8 raw, 1=int32, 2=bf16, 3=f32

// ---------------------------------------------------------------------------
__device__ __forceinline__ uint32_t smem_u32(const void* p) {
    uint32_t a;
    asm("{ .reg .u64 t; cvta.to.shared.u64 t, %1; cvt.u32.u64 %0, t; }" : "=r"(a) : "l"(p));
    return a;
}

__device__ __forceinline__ void cp16(uint32_t dst, const void* src) {
    asm volatile("cp.async.cg.shared.global [%0], [%1], 16;" :: "r"(dst), "l"(src));
}

__device__ __forceinline__ void ldsm_x4(uint32_t* r, uint32_t addr) {
    asm volatile("ldmatrix.sync.aligned.m8n8.x4.shared.b16 {%0,%1,%2,%3}, [%4];"
                 : "=r"(r[0]), "=r"(r[1]), "=r"(r[2]), "=r"(r[3]) : "r"(addr));
}

__device__ __forceinline__ void mma_bf16_k16(float* c, const uint32_t* a, uint32_t b0, uint32_t b1) {
    asm volatile(
        "mma.sync.aligned.m16n8k16.row.col.f32.bf16.bf16.f32 "
        "{%0,%1,%2,%3}, {%4,%5,%6,%7}, {%8,%9}, {%0,%1,%2,%3};"
        : "+f"(c[0]), "+f"(c[1]), "+f"(c[2]), "+f"(c[3])
        : "r"(a[0]), "r"(a[1]), "r"(a[2]), "r"(a[3]), "r"(b0), "r"(b1));
}

// ---------------------------------------------------------------------------
// Weight format autodetect (proven necessary in round 4)
// ---------------------------------------------------------------------------
__global__ void detect_kernel(const void* w) {
    __shared__ int ok32, okf32, okbf;
    int tid = threadIdx.x;
    if (tid == 0) { ok32 = 1; okf32 = 1; okbf = 1; }
    __syncthreads();
    const int*            wi = (const int*)w;
    const float*          wf = (const float*)w;
    const __nv_bfloat16*  wb = (const __nv_bfloat16*)w;
#pragma unroll
    for (int i = 0; i < 4; i++) {
        int idx = tid * 4 + i;
        int v = wi[idx];
        if (v < -128 || v > 127) ok32 = 0;
        float f = wf[idx];
        if (!(f == rintf(f)) || f < -128.0f || f > 127.0f) okf32 = 0;
        float b = __bfloat162float(wb[idx]);
        if (!(b == rintf(b)) || b < -128.0f || b > 127.0f) okbf = 0;
    }
    __syncthreads();
    if (tid == 0)
        g_wmode = ok32 ? 1 : (okf32 ? 3 : (okbf ? 2 : 0));
}

// Pack weight (any transport format) directly to bf16. 16 elems per thread.
__global__ void __launch_bounds__(256) pack_kernel(const void* w) {
    size_t g = (size_t)blockIdx.x * blockDim.x + threadIdx.x;
    if (g * 16 >= W_ELEMS) return;
    int mode = g_wmode;
    float f[16];
    if (mode == 0) {
        int8_t b[16];
        *(int4*)b = ((const int4*)w)[g];
#pragma unroll
        for (int j = 0; j < 16; j++) f[j] = (float)b[j];
    } else if (mode == 1) {
        const int4* wi = (const int4*)w + g * 4;
#pragma unroll
        for (int j = 0; j < 4; j++) {
            int4 v = wi[j];
            f[j * 4 + 0] = (float)(int8_t)v.x; f[j * 4 + 1] = (float)(int8_t)v.y;
            f[j * 4 + 2] = (float)(int8_t)v.z; f[j * 4 + 3] = (float)(int8_t)v.w;
        }
    } else if (mode == 2) {
        const __nv_bfloat16* wb = (const __nv_bfloat16*)w + g * 16;
#pragma unroll
        for (int j = 0; j < 16; j++) f[j] = __bfloat162float(wb[j]);
    } else {
        const float4* wf = (const float4*)w + g * 4;
#pragma unroll
        for (int j = 0; j < 4; j++) {
            float4 v = wf[j];
            f[j * 4 + 0] = v.x; f[j * 4 + 1] = v.y;
            f[j * 4 + 2] = v.z; f[j * 4 + 3] = v.w;
        }
    }
    uint32_t o[8];
#pragma unroll
    for (int j = 0; j < 8; j++) {
        __nv_bfloat162 h = __floats2bfloat162_rn(f[2 * j], f[2 * j + 1]);
        o[j] = *(uint32_t*)&h;
    }
    uint4* dst = (uint4*)(g_wbf + g * 16);
    dst[0] = make_uint4(o[0], o[1], o[2], o[3]);
    dst[1] = make_uint4(o[4], o[5], o[6], o[7]);
}

// ---------------------------------------------------------------------------
// Kernel 1: per-token dynamic quantization -> bf16 (int-valued)
// ---------------------------------------------------------------------------
__device__ __forceinline__ float q8f(float x, float s) {
    float r = rintf(__fdiv_rn(x, s));
    return fminf(fmaxf(r, -128.0f), 127.0f);
}

__global__ void __launch_bounds__(256) quant_kernel(const float* __restrict__ x) {
    int t = blockIdx.x;
    int tid = threadIdx.x;
    const float4* xr = (const float4*)(x + (size_t)t * KDIM);
    float4 v[4];
    float am = 0.0f;
#pragma unroll
    for (int i = 0; i < 4; i++) {
        v[i] = xr[tid * 4 + i];
        am = fmaxf(am, fmaxf(fmaxf(fabsf(v[i].x), fabsf(v[i].y)),
                             fmaxf(fabsf(v[i].z), fabsf(v[i].w))));
    }
    __shared__ float red[256];
    red[tid] = am;
    __syncthreads();
    for (int s = 128; s > 0; s >>= 1) {
        if (tid < s) red[tid] = fmaxf(red[tid], red[tid + s]);
        __syncthreads();
    }
    float s = fmaxf(__fdiv_rn(red[0], 127.0f), 1e-8f);
    if (tid == 0) g_ascale[t] = s;

    float q[16];
    q[0] = q8f(v[0].x, s);  q[1] = q8f(v[0].y, s);  q[2] = q8f(v[0].z, s);  q[3] = q8f(v[0].w, s);
    q[4] = q8f(v[1].x, s);  q[5] = q8f(v[1].y, s);  q[6] = q8f(v[1].z, s);  q[7] = q8f(v[1].w, s);
    q[8] = q8f(v[2].x, s);  q[9] = q8f(v[2].y, s);  q[10] = q8f(v[2].z, s); q[11] = q8f(v[2].w, s);
    q[12] = q8f(v[3].x, s); q[13] = q8f(v[3].y, s); q[14] = q8f(v[3].z, s); q[15] = q8f(v[3].w, s);

    uint32_t h[8];
#pragma unroll
    for (int j = 0; j < 8; j++) {
        __nv_bfloat162 hb = __floats2bfloat162_rn(q[2 * j], q[2 * j + 1]);
        h[j] = *(uint32_t*)&hb;
    }
    uint4* dst = (uint4*)(g_xbf + (size_t)t * KDIM + tid * 16);
    dst[0] = make_uint4(h[0], h[1], h[2], h[3]);
    dst[1] = make_uint4(h[4], h[5], h[6], h[7]);
}

// ---------------------------------------------------------------------------
// GEMM: bf16 HMMA m16n8k16, 128x256 tile, 512 threads, 3-stage cp.async
// ---------------------------------------------------------------------------
__device__ __forceinline__ void copy_chunk(const __nv_bfloat16* abase_g,
                                           const __nv_bfloat16* bbase_g,
                                           int c, int stage, uint32_t sb, int tid) {
    uint32_t st = sb + SM_AB + stage * STAGE_BYTES;
    const char* asrc = (const char*)abase_g + (size_t)c * 128;
#pragma unroll
    for (int i = 0; i < 2; i++) {
        int idx = tid + i * 512;
        int row = idx >> 3, u = idx & 7;
        cp16(st + row * ROWB + u * 16, asrc + (size_t)row * (KDIM * 2) + u * 16);
    }
    const char* bsrc = (const char*)bbase_g + (size_t)c * 128;
    uint32_t bb = st + A_BYTES;
#pragma unroll
    for (int i = 0; i < 4; i++) {
        int idx = tid + i * 512;
        int row = idx >> 3, u = idx & 7;
        cp16(bb + row * ROWB + u * 16, bsrc + (size_t)row * (KDIM * 2) + u * 16);
    }
}

__global__ void __launch_bounds__(512, 1) hmma_gemm(const float* __restrict__ wscale,
                                                    const float* __restrict__ bias,
                                                    float* __restrict__ out) {
    extern __shared__ char smem[];
    uint32_t sb = smem_u32(smem);
    int tid = threadIdx.x, wid = tid >> 5, lane = tid & 31;
    int m0 = blockIdx.y * TILE_M;
    int n0 = blockIdx.x * TILE_N;
    int wm = wid & 3, wn = wid >> 2;

    float* smem_ws = (float*)(smem + SM_WS);
    float* smem_bs = (float*)(smem + SM_BS);
    if (tid < 256)      smem_ws[tid] = wscale[n0 + tid];
    else                smem_bs[tid - 256] = bias[n0 + tid - 256];

    int g = lane >> 3, lr = lane & 7;
    uint32_t aoff = (uint32_t)((wm * 32 + (g & 1) * 8 + lr) * ROWB + (g >> 1) * 16);
    uint32_t boff = (uint32_t)(A_BYTES + (wn * 64 + (g >> 1) * 8 + lr) * ROWB + (g & 1) * 16);

    float acc[2][8][4];
#pragma unroll
    for (int f = 0; f < 2; f++)
#pragma unroll
        for (int nf = 0; nf < 8; nf++)
#pragma unroll
            for (int i = 0; i < 4; i++) acc[f][nf][i] = 0.0f;

    const __nv_bfloat16* Ag = g_xbf + (size_t)m0 * KDIM;
    const __nv_bfloat16* Bg = g_wbf + (size_t)n0 * KDIM;

    copy_chunk(Ag, Bg, 0, 0, sb, tid);
    asm volatile("cp.async.commit_group;" ::: "memory");
    copy_chunk(Ag, Bg, 1, 1, sb, tid);
    asm volatile("cp.async.commit_group;" ::: "memory");

    for (int c = 0; c < NCH; c++) {
        if (c + 2 < NCH) {
            copy_chunk(Ag, Bg, c + 2, (c + 2) % NSTAGE, sb, tid);
            asm volatile("cp.async.commit_group;" ::: "memory");
        }
        if (c <= NCH - 3)      asm volatile("cp.async.wait_group 2;" ::: "memory");
        else if (c == NCH - 2) asm volatile("cp.async.wait_group 1;" ::: "memory");
        else                   asm volatile("cp.async.wait_group 0;" ::: "memory");
        __syncthreads();

        uint32_t st = sb + SM_AB + (c % NSTAGE) * STAGE_BYTES;
#pragma unroll
        for (int ks = 0; ks < 4; ks++) {          // 4 x k16 (32 B) per 128-B chunk
            uint32_t a[2][4];
#pragma unroll
            for (int f = 0; f < 2; f++)
                ldsm_x4(a[f], st + aoff + f * (16 * ROWB) + ks * 32);
            uint32_t b[4][4];
#pragma unroll
            for (int q = 0; q < 4; q++)
                ldsm_x4(b[q], st + boff + q * (16 * ROWB) + ks * 32);
#pragma unroll
            for (int f = 0; f < 2; f++)
#pragma unroll
                for (int q = 0; q < 4; q++) {
                    mma_bf16_k16(acc[f][2 * q],     a[f], b[q][0], b[q][1]);
                    mma_bf16_k16(acc[f][2 * q + 1], a[f], b[q][2], b[q][3]);
                }
        }
        __syncthreads();
    }

    int lrow = lane >> 2, lcol2 = (lane & 3) * 2;
#pragma unroll
    for (int f = 0; f < 2; f++) {
        int mA = m0 + wm * 32 + f * 16 + lrow;
        float as0 = g_ascale[mA];
        float as1 = g_ascale[mA + 8];
#pragma unroll
        for (int nf = 0; nf < 8; nf++) {
            int col = wn * 64 + nf * 8 + lcol2;
            float ws0 = smem_ws[col], ws1 = smem_ws[col + 1];
            float bs0 = smem_bs[col], bs1 = smem_bs[col + 1];
            float2 v0, v1;
            v0.x = fmaf(acc[f][nf][0] * as0, ws0, bs0);
            v0.y = fmaf(acc[f][nf][1] * as0, ws1, bs1);
            v1.x = fmaf(acc[f][nf][2] * as1, ws0, bs0);
            v1.y = fmaf(acc[f][nf][3] * as1, ws1, bs1);
            *(float2*)(out + (size_t)mA * NDIM + n0 + col) = v0;
            *(float2*)(out + (size_t)(mA + 8) * NDIM + n0 + col) = v1;
        }
    }
}

// ---------------------------------------------------------------------------
extern "C" void kernel_launch(void* const* d_in, const int* in_sizes, int n_in,
                              void* d_out, int out_size) {
    const float* x;
    const float* bs;
    if (in_sizes[0] == NDIM) {           // alphabetical: bias first
        bs = (const float*)d_in[0];
        x  = (const float*)d_in[3];
    } else {                             // dict order: x first
        x  = (const float*)d_in[0];
        bs = (const float*)d_in[3];
    }
    const void*  w  = d_in[1];
    const float* ws = (const float*)d_in[2];
    float* out = (float*)d_out;

    cudaFuncSetAttribute(hmma_gemm, cudaFuncAttributeMaxDynamicSharedMemorySize, SMEM_TOTAL);

    detect_kernel<<<1, 256>>>(w);
    pack_kernel<<<(int)((W_ELEMS / 16 + 255) / 256), 256>>>(w);
    quant_kernel<<<TOK, 256>>>(x);
    dim3 grid(NDIM / TILE_N, TOK / TILE_M);   // (48, 32)
    hmma_gemm<<<grid, 512, SMEM_TOTAL>>>(ws, bs, out);
}

// round 8
// speedup vs baseline: 4.7821x; 1.0947x over previous
#include <cuda_runtime.h>
#include <cuda_bf16.h>
#include <cstdint>

// ---------------------------------------------------------------------------
// W8A8 dynamic-quant linear:  y = (q8(x) @ W^T) * act_scale * w_scale + bias
// TOK=4096, K=4096, OUT(N)=12288
//
// Round 8: all-HMMA (proven). GEMM restructured for arithmetic intensity:
//   - 64x64 warp tiles (8 warps / 256 thr, block tile 128x256)
//     -> 0.25 ldsm/MMA (was 0.375), LDS traffic -33%
//   - 256-B K-chunks, 2-stage double buffer, ONE syncthreads per chunk
//     (barrier bounds warp skew to 1 iter; writer stage != reader stage)
// ---------------------------------------------------------------------------

#define TOK   4096
#define KDIM  4096
#define NDIM  12288

#define TILE_M 128
#define TILE_N 256
#define NCH    32                // 256-B (128-elem) bf16 K-chunks
#define KCB    256               // chunk bytes

#define ROWB   272               // 256 B K-chunk + 16 B pad
#define A_BYTES (TILE_M * ROWB)  // 34816
#define B_BYTES (TILE_N * ROWB)  // 69632
#define STAGE_BYTES (A_BYTES + B_BYTES)   // 104448

// SMEM layout (bytes)
#define SM_WS 0                  // 256 floats
#define SM_BS 1024               // 256 floats
#define SM_AB 2048               // 2 stages
#define SMEM_TOTAL (SM_AB + 2 * STAGE_BYTES)   // 210944

#define W_ELEMS ((size_t)NDIM * KDIM)    // 50331648

// Scratch (module globals -- allocation-free per harness rules)
__device__ __nv_bfloat16 g_xbf[(size_t)TOK * KDIM];
__device__ __nv_bfloat16 g_wbf[W_ELEMS];
__device__ float         g_ascale[TOK];
__device__ int           g_wmode;   // 0=int8 raw, 1=int32, 2=bf16, 3=f32

// ---------------------------------------------------------------------------
__device__ __forceinline__ uint32_t smem_u32(const void* p) {
    uint32_t a;
    asm("{ .reg .u64 t; cvta.to.shared.u64 t, %1; cvt.u32.u64 %0, t; }" : "=r"(a) : "l"(p));
    return a;
}

__device__ __forceinline__ void cp16(uint32_t dst, const void* src) {
    asm volatile("cp.async.cg.shared.global [%0], [%1], 16;" :: "r"(dst), "l"(src));
}

__device__ __forceinline__ void ldsm_x4(uint32_t* r, uint32_t addr) {
    asm volatile("ldmatrix.sync.aligned.m8n8.x4.shared.b16 {%0,%1,%2,%3}, [%4];"
                 : "=r"(r[0]), "=r"(r[1]), "=r"(r[2]), "=r"(r[3]) : "r"(addr));
}

__device__ __forceinline__ void mma_bf16_k16(float* c, const uint32_t* a, uint32_t b0, uint32_t b1) {
    asm volatile(
        "mma.sync.aligned.m16n8k16.row.col.f32.bf16.bf16.f32 "
        "{%0,%1,%2,%3}, {%4,%5,%6,%7}, {%8,%9}, {%0,%1,%2,%3};"
        : "+f"(c[0]), "+f"(c[1]), "+f"(c[2]), "+f"(c[3])
        : "r"(a[0]), "r"(a[1]), "r"(a[2]), "r"(a[3]), "r"(b0), "r"(b1));
}

// ---------------------------------------------------------------------------
// Weight format autodetect + direct-to-bf16 pack (proven rounds 4/7)
// ---------------------------------------------------------------------------
__global__ void detect_kernel(const void* w) {
    __shared__ int ok32, okf32, okbf;
    int tid = threadIdx.x;
    if (tid == 0) { ok32 = 1; okf32 = 1; okbf = 1; }
    __syncthreads();
    const int*            wi = (const int*)w;
    const float*          wf = (const float*)w;
    const __nv_bfloat16*  wb = (const __nv_bfloat16*)w;
#pragma unroll
    for (int i = 0; i < 4; i++) {
        int idx = tid * 4 + i;
        int v = wi[idx];
        if (v < -128 || v > 127) ok32 = 0;
        float f = wf[idx];
        if (!(f == rintf(f)) || f < -128.0f || f > 127.0f) okf32 = 0;
        float b = __bfloat162float(wb[idx]);
        if (!(b == rintf(b)) || b < -128.0f || b > 127.0f) okbf = 0;
    }
    __syncthreads();
    if (tid == 0)
        g_wmode = ok32 ? 1 : (okf32 ? 3 : (okbf ? 2 : 0));
}

__global__ void __launch_bounds__(256) pack_kernel(const void* w) {
    size_t g = (size_t)blockIdx.x * blockDim.x + threadIdx.x;
    if (g * 16 >= W_ELEMS) return;
    int mode = g_wmode;
    float f[16];
    if (mode == 0) {
        int8_t b[16];
        *(int4*)b = ((const int4*)w)[g];
#pragma unroll
        for (int j = 0; j < 16; j++) f[j] = (float)b[j];
    } else if (mode == 1) {
        const int4* wi = (const int4*)w + g * 4;
#pragma unroll
        for (int j = 0; j < 4; j++) {
            int4 v = wi[j];
            f[j * 4 + 0] = (float)(int8_t)v.x; f[j * 4 + 1] = (float)(int8_t)v.y;
            f[j * 4 + 2] = (float)(int8_t)v.z; f[j * 4 + 3] = (float)(int8_t)v.w;
        }
    } else if (mode == 2) {
        const __nv_bfloat16* wb = (const __nv_bfloat16*)w + g * 16;
#pragma unroll
        for (int j = 0; j < 16; j++) f[j] = __bfloat162float(wb[j]);
    } else {
        const float4* wf = (const float4*)w + g * 4;
#pragma unroll
        for (int j = 0; j < 4; j++) {
            float4 v = wf[j];
            f[j * 4 + 0] = v.x; f[j * 4 + 1] = v.y;
            f[j * 4 + 2] = v.z; f[j * 4 + 3] = v.w;
        }
    }
    uint32_t o[8];
#pragma unroll
    for (int j = 0; j < 8; j++) {
        __nv_bfloat162 h = __floats2bfloat162_rn(f[2 * j], f[2 * j + 1]);
        o[j] = *(uint32_t*)&h;
    }
    uint4* dst = (uint4*)(g_wbf + g * 16);
    dst[0] = make_uint4(o[0], o[1], o[2], o[3]);
    dst[1] = make_uint4(o[4], o[5], o[6], o[7]);
}

// ---------------------------------------------------------------------------
// Kernel 1: per-token dynamic quantization -> bf16 (int-valued)
// ---------------------------------------------------------------------------
__device__ __forceinline__ float q8f(float x, float s) {
    float r = rintf(__fdiv_rn(x, s));
    return fminf(fmaxf(r, -128.0f), 127.0f);
}

__global__ void __launch_bounds__(256) quant_kernel(const float* __restrict__ x) {
    int t = blockIdx.x;
    int tid = threadIdx.x;
    const float4* xr = (const float4*)(x + (size_t)t * KDIM);
    float4 v[4];
    float am = 0.0f;
#pragma unroll
    for (int i = 0; i < 4; i++) {
        v[i] = xr[tid * 4 + i];
        am = fmaxf(am, fmaxf(fmaxf(fabsf(v[i].x), fabsf(v[i].y)),
                             fmaxf(fabsf(v[i].z), fabsf(v[i].w))));
    }
    __shared__ float red[256];
    red[tid] = am;
    __syncthreads();
    for (int s = 128; s > 0; s >>= 1) {
        if (tid < s) red[tid] = fmaxf(red[tid], red[tid + s]);
        __syncthreads();
    }
    float s = fmaxf(__fdiv_rn(red[0], 127.0f), 1e-8f);
    if (tid == 0) g_ascale[t] = s;

    float q[16];
    q[0] = q8f(v[0].x, s);  q[1] = q8f(v[0].y, s);  q[2] = q8f(v[0].z, s);  q[3] = q8f(v[0].w, s);
    q[4] = q8f(v[1].x, s);  q[5] = q8f(v[1].y, s);  q[6] = q8f(v[1].z, s);  q[7] = q8f(v[1].w, s);
    q[8] = q8f(v[2].x, s);  q[9] = q8f(v[2].y, s);  q[10] = q8f(v[2].z, s); q[11] = q8f(v[2].w, s);
    q[12] = q8f(v[3].x, s); q[13] = q8f(v[3].y, s); q[14] = q8f(v[3].z, s); q[15] = q8f(v[3].w, s);

    uint32_t h[8];
#pragma unroll
    for (int j = 0; j < 8; j++) {
        __nv_bfloat162 hb = __floats2bfloat162_rn(q[2 * j], q[2 * j + 1]);
        h[j] = *(uint32_t*)&hb;
    }
    uint4* dst = (uint4*)(g_xbf + (size_t)t * KDIM + tid * 16);
    dst[0] = make_uint4(h[0], h[1], h[2], h[3]);
    dst[1] = make_uint4(h[4], h[5], h[6], h[7]);
}

// ---------------------------------------------------------------------------
// GEMM: bf16 HMMA, 128x256 tile, 256 thr (8 warps x 64x64), 2-stage 256B chunks
// ---------------------------------------------------------------------------
__device__ __forceinline__ void copy_chunk(const __nv_bfloat16* abase_g,
                                           const __nv_bfloat16* bbase_g,
                                           int c, int stage, uint32_t sb, int tid) {
    uint32_t st = sb + SM_AB + stage * STAGE_BYTES;
    // A: 128 rows x 256 B = 2048 cp16 -> 8 per thread
    const char* asrc = (const char*)abase_g + (size_t)c * KCB;
#pragma unroll
    for (int i = 0; i < 8; i++) {
        int idx = tid + i * 256;
        int row = idx >> 4, u = idx & 15;
        cp16(st + row * ROWB + u * 16, asrc + (size_t)row * (KDIM * 2) + u * 16);
    }
    // B: 256 rows x 256 B = 4096 cp16 -> 16 per thread
    const char* bsrc = (const char*)bbase_g + (size_t)c * KCB;
    uint32_t bb = st + A_BYTES;
#pragma unroll
    for (int i = 0; i < 16; i++) {
        int idx = tid + i * 256;
        int row = idx >> 4, u = idx & 15;
        cp16(bb + row * ROWB + u * 16, bsrc + (size_t)row * (KDIM * 2) + u * 16);
    }
}

__global__ void __launch_bounds__(256, 1) hmma_gemm(const float* __restrict__ wscale,
                                                    const float* __restrict__ bias,
                                                    float* __restrict__ out) {
    extern __shared__ char smem[];
    uint32_t sb = smem_u32(smem);
    int tid = threadIdx.x, wid = tid >> 5, lane = tid & 31;
    int m0 = blockIdx.y * TILE_M;
    int n0 = blockIdx.x * TILE_N;
    int wm = wid & 1;            // 2 M-strips of 64
    int wn = wid >> 1;           // 4 N-strips of 64

    float* smem_ws = (float*)(smem + SM_WS);
    float* smem_bs = (float*)(smem + SM_BS);
    smem_ws[tid] = wscale[n0 + tid];
    smem_bs[tid] = bias[n0 + tid];

    int g = lane >> 3, lr = lane & 7;
    // A ldsm (16x16 tile): {r+0 k0-7, r+8 k0-7, r+0 k8-15, r+8 k8-15}
    uint32_t aoff = (uint32_t)((wm * 64 + (g & 1) * 8 + lr) * ROWB + (g >> 1) * 16);
    // B ldsm (16n x 16k): {n+0 k0-7, n+0 k8-15, n+8 k0-7, n+8 k8-15}
    uint32_t boff = (uint32_t)(A_BYTES + (wn * 64 + (g >> 1) * 8 + lr) * ROWB + (g & 1) * 16);

    float acc[4][8][4];
#pragma unroll
    for (int f = 0; f < 4; f++)
#pragma unroll
        for (int nf = 0; nf < 8; nf++)
#pragma unroll
            for (int i = 0; i < 4; i++) acc[f][nf][i] = 0.0f;

    const __nv_bfloat16* Ag = g_xbf + (size_t)m0 * KDIM;
    const __nv_bfloat16* Bg = g_wbf + (size_t)n0 * KDIM;

    copy_chunk(Ag, Bg, 0, 0, sb, tid);
    asm volatile("cp.async.commit_group;" ::: "memory");

    for (int c = 0; c < NCH; c++) {
        asm volatile("cp.async.wait_group 0;" ::: "memory");
        __syncthreads();          // chunk c ready AND all warps done with c-1
        if (c + 1 < NCH) {
            copy_chunk(Ag, Bg, c + 1, (c + 1) & 1, sb, tid);
            asm volatile("cp.async.commit_group;" ::: "memory");
        }
        uint32_t st = sb + SM_AB + (c & 1) * STAGE_BYTES;
#pragma unroll
        for (int ks = 0; ks < 8; ks++) {      // 8 x k16 (32 B) per 256-B chunk
            uint32_t a[4][4];
#pragma unroll
            for (int f = 0; f < 4; f++)
                ldsm_x4(a[f], st + aoff + f * (16 * ROWB) + ks * 32);
            uint32_t b[4][4];
#pragma unroll
            for (int q = 0; q < 4; q++)
                ldsm_x4(b[q], st + boff + q * (16 * ROWB) + ks * 32);
#pragma unroll
            for (int f = 0; f < 4; f++)
#pragma unroll
                for (int q = 0; q < 4; q++) {
                    mma_bf16_k16(acc[f][2 * q],     a[f], b[q][0], b[q][1]);
                    mma_bf16_k16(acc[f][2 * q + 1], a[f], b[q][2], b[q][3]);
                }
        }
    }

    int lrow = lane >> 2, lcol2 = (lane & 3) * 2;
#pragma unroll
    for (int f = 0; f < 4; f++) {
        int mA = m0 + wm * 64 + f * 16 + lrow;
        float as0 = g_ascale[mA];
        float as1 = g_ascale[mA + 8];
#pragma unroll
        for (int nf = 0; nf < 8; nf++) {
            int col = wn * 64 + nf * 8 + lcol2;
            float ws0 = smem_ws[col], ws1 = smem_ws[col + 1];
            float bs0 = smem_bs[col], bs1 = smem_bs[col + 1];
            float2 v0, v1;
            v0.x = fmaf(acc[f][nf][0] * as0, ws0, bs0);
            v0.y = fmaf(acc[f][nf][1] * as0, ws1, bs1);
            v1.x = fmaf(acc[f][nf][2] * as1, ws0, bs0);
            v1.y = fmaf(acc[f][nf][3] * as1, ws1, bs1);
            *(float2*)(out + (size_t)mA * NDIM + n0 + col) = v0;
            *(float2*)(out + (size_t)(mA + 8) * NDIM + n0 + col) = v1;
        }
    }
}

// ---------------------------------------------------------------------------
extern "C" void kernel_launch(void* const* d_in, const int* in_sizes, int n_in,
                              void* d_out, int out_size) {
    const float* x;
    const float* bs;
    if (in_sizes[0] == NDIM) {           // alphabetical: bias first
        bs = (const float*)d_in[0];
        x  = (const float*)d_in[3];
    } else {                             // dict order: x first
        x  = (const float*)d_in[0];
        bs = (const float*)d_in[3];
    }
    const void*  w  = d_in[1];
    const float* ws = (const float*)d_in[2];
    float* out = (float*)d_out;

    cudaFuncSetAttribute(hmma_gemm, cudaFuncAttributeMaxDynamicSharedMemorySize, SMEM_TOTAL);

    detect_kernel<<<1, 256>>>(w);
    pack_kernel<<<(int)((W_ELEMS / 16 + 255) / 256), 256>>>(w);
    quant_kernel<<<TOK, 256>>>(x);
    dim3 grid(NDIM / TILE_N, TOK / TILE_M);   // (48, 32)
    hmma_gemm<<<grid, 256, SMEM_TOTAL>>>(ws, bs, out);
}